// round 11
// baseline (speedup 1.0000x reference)
#include <cuda_runtime.h>
#include <cuda_bf16.h>
#include <math.h>

// Problem constants
#define NSITES 1024
#define NC6 64               // 6-site codes (base table)
#define NC4 16               // 4-site tail codes (base table)
#define N12 4096             // 12-site codes: 2^12
#define NSTEPS 86            // 85 twelve-site + 1 four-site tail
// Base table (B-fragment layout, bf16x2): used by build12 + tail mirror
__device__ unsigned g_table[(NC6 + NC4) * 512];
// 12-site table in GLOBAL (L2-resident, 8.4 MB): codes 0..4095 are 12-site,
// codes 4096..4111 mirror the 4-site tail entries.
__device__ unsigned g12_table[(N12 + NC4) * 512];

// ---------------------------------------------------------------------------
// build1: 6-site (blocks 0..63) and 4-site (blocks 64..79) products,
// Y = P - I stored as bf16 B-fragments. 4-site entries also mirrored to g12.
// ---------------------------------------------------------------------------
__global__ void build_table_kernel(const float* __restrict__ A) {
    __shared__ float M[2][32][32];
    __shared__ float P[2][32][32];
    const int tid = threadIdx.x;          // 1024 threads
    const int r = tid >> 5, c = tid & 31;

    M[0][r][c] = A[r * 32 + c];
    M[1][r][c] = A[1024 + r * 32 + c];
    __syncthreads();

    const bool is6 = blockIdx.x < NC6;
    const int code = is6 ? blockIdx.x : (blockIdx.x - NC6);
    const int nsit = is6 ? 6 : 4;

    P[0][r][c] = M[code & 1][r][c];
    __syncthreads();

    int cur = 0;
    for (int t = 1; t < nsit; t++) {
        const int bsel = (code >> t) & 1;
        float acc = 0.f;
        #pragma unroll
        for (int k = 0; k < 32; k++) acc += P[cur][r][k] * M[bsel][k][c];
        P[1 - cur][r][c] = acc;
        cur ^= 1;
        __syncthreads();
    }
    if (tid < 512) {
        const int l = tid >> 4;           // lane
        const int ridx = tid & 15;        // reg 0..15
        const int tig = l & 3, g = l >> 2;
        const int kc = ridx >> 3, nt = (ridx >> 1) & 3, h = ridx & 1;
        const int row = 16 * kc + 2 * tig + 8 * h;
        const int col = 8 * nt + g;
        const float lo = P[cur][row][col]     - (row     == col ? 1.f : 0.f);
        const float hi = P[cur][row + 1][col] - (row + 1 == col ? 1.f : 0.f);
        unsigned v;
        asm("cvt.rn.bf16x2.f32 %0, %1, %2;" : "=r"(v) : "f"(hi), "f"(lo));
        const int q = ridx >> 2, j = ridx & 3;
        const int idx = q * 128 + l * 4 + j;
        g_table[blockIdx.x * 512 + idx] = v;
        if (!is6) g12_table[(N12 + code) * 512 + idx] = v;   // tail mirror
    }
}

// ---------------------------------------------------------------------------
// build2: 12-site table from pairs of 6-site entries.
// Z(ca + 64*cb) = (I+Ya)(I+Yb) - I  (fp32 product of bf16 entries).
// grid (64, 8): block (ca, oct) handles cb = oct*8..oct*8+7.
// ---------------------------------------------------------------------------
__device__ __forceinline__ void decode_entry(float Pm[32][32], int code, int tid) {
    if (tid < 512) {
        const unsigned u = g_table[code * 512 + tid];
        const int l = (tid & 127) >> 2, j = tid & 3, q = tid >> 7;
        const int rr = 4 * q + j;
        const int kc = rr >> 3, nt = (rr >> 1) & 3, h = rr & 1;
        const int tig = l & 3, g = l >> 2;
        const int row = 16 * kc + 2 * tig + 8 * h;
        const int col = 8 * nt + g;
        Pm[row][col]     = __uint_as_float(u << 16)          + (row     == col ? 1.f : 0.f);
        Pm[row + 1][col] = __uint_as_float(u & 0xFFFF0000u)  + (row + 1 == col ? 1.f : 0.f);
    }
}

__global__ void build12_kernel() {
    __shared__ float Pa[32][32], Pb[32][32], Zs[32][32];
    const int tid = threadIdx.x;          // 1024 threads
    const int r = tid >> 5, c = tid & 31;
    const int ca = blockIdx.x;            // first 6 sites (low bits)

    decode_entry(Pa, ca, tid);
    __syncthreads();

    for (int i = 0; i < 8; i++) {
        const int cb = blockIdx.y * 8 + i;   // next 6 sites (high bits)
        decode_entry(Pb, cb, tid);
        __syncthreads();
        float acc = 0.f;
        #pragma unroll
        for (int k = 0; k < 32; k++) acc += Pa[r][k] * Pb[k][c];
        Zs[r][c] = acc - (r == c ? 1.f : 0.f);
        __syncthreads();
        if (tid < 512) {
            const int l = tid >> 4, ridx = tid & 15;
            const int tig = l & 3, g = l >> 2;
            const int kc = ridx >> 3, nt = (ridx >> 1) & 3, h = ridx & 1;
            const int row = 16 * kc + 2 * tig + 8 * h;
            const int col = 8 * nt + g;
            unsigned v;
            asm("cvt.rn.bf16x2.f32 %0, %1, %2;"
                : "=r"(v) : "f"(Zs[row + 1][col]), "f"(Zs[row][col]));
            const int q = ridx >> 2, j = ridx & 3;
            g12_table[(cb * 64 + ca) * 512 + q * 128 + l * 4 + j] = v;
        }
        __syncthreads();
    }
}

// ---------------------------------------------------------------------------
// Main kernel: ONE sample per warp, 28 warps/CTA, 1 CTA/SM.
// 12-site steps; B entries streamed from L2 via per-warp 3-stage cp.async ring.
// Per step:  M <- mma( bf16(M) , Z_code ) + M   ==  M @ (I + Z)   (C exact)
// ---------------------------------------------------------------------------
__device__ __forceinline__ void mma_bf16(float* d, const unsigned* a,
                                         unsigned b0, unsigned b1) {
    asm("mma.sync.aligned.m16n8k16.row.col.f32.bf16.bf16.f32 "
        "{%0,%1,%2,%3}, {%4,%5,%6,%7}, {%8,%9}, {%0,%1,%2,%3};"
        : "+f"(d[0]), "+f"(d[1]), "+f"(d[2]), "+f"(d[3])
        : "r"(a[0]), "r"(a[1]), "r"(a[2]), "r"(a[3]), "r"(b0), "r"(b1));
}

__device__ __forceinline__ void cvt_a(unsigned a[16], const float x[32]) {
    #pragma unroll
    for (int mt = 0; mt < 2; mt++)
        #pragma unroll
        for (int kc = 0; kc < 2; kc++)
            #pragma unroll
            for (int j = 0; j < 4; j++) {
                const int o = j >> 1, ih = j & 1;
                const int xi = mt * 16 + (2 * kc + o) * 4 + 2 * ih;
                asm("cvt.rn.bf16x2.f32 %0, %1, %2;"
                    : "=r"(a[mt * 8 + kc * 4 + j])
                    : "f"(x[xi + 1]), "f"(x[xi]));
            }
}

__device__ __forceinline__ void mma_half(float x[32], const unsigned a[16],
                                         int abase, uint4 ta, uint4 tb) {
    #pragma unroll
    for (int mt = 0; mt < 2; mt++) {
        const unsigned* av = a + mt * 8 + abase;
        mma_bf16(x + mt*16 + 0,  av, ta.x, ta.y);
        mma_bf16(x + mt*16 + 4,  av, ta.z, ta.w);
        mma_bf16(x + mt*16 + 8,  av, tb.x, tb.y);
        mma_bf16(x + mt*16 + 12, av, tb.z, tb.w);
    }
}

// 2KB entry -> smem stage, 16B per lane x4 chunks (identity byte copy)
__device__ __forceinline__ void prefetch_entry(unsigned dst,
                                               const unsigned* entry, int lane) {
    const unsigned* sp = entry + lane * 4;
    const unsigned dp = dst + lane * 16;
    asm volatile(
        "cp.async.cg.shared.global [%0], [%1], 16;\n\t"
        "cp.async.cg.shared.global [%2], [%3], 16;\n\t"
        "cp.async.cg.shared.global [%4], [%5], 16;\n\t"
        "cp.async.cg.shared.global [%6], [%7], 16;\n\t"
        :: "r"(dp),        "l"(sp),
           "r"(dp + 512),  "l"(sp + 128),
           "r"(dp + 1024), "l"(sp + 256),
           "r"(dp + 1536), "l"(sp + 384)
        : "memory");
}
#define CP_COMMIT()  asm volatile("cp.async.commit_group;" ::: "memory")
#define CP_WAIT1()   asm volatile("cp.async.wait_group 1;" ::: "memory")

#define NWARPS 28
#define RING_BYTES (NWARPS * 3 * 2048)        // 172 KB, 3 stages x 2KB / warp
#define MSK_BYTES (NWARPS * 32 * 4)           // 3.5 KB
#define CW_BYTES (NWARPS * 88 * 2)            // uint16 codes, padded
#define SMEM_BYTES (RING_BYTES + MSK_BYTES + CW_BYTES)
#define GRID 148
#define NTHREADS (NWARPS * 32)                // 896

__global__ void __launch_bounds__(NTHREADS, 1)
mps_kernel(const float* __restrict__ s, float* __restrict__ out) {
    extern __shared__ unsigned char smem_raw[];
    const int lane = threadIdx.x & 31;
    const int warp = threadIdx.x >> 5;
    const int b = warp * GRID + blockIdx.x;   // one sample per warp
    if (b >= 4096) return;                    // all smem is warp-private
    const int g = lane >> 2, tig = lane & 3;

    uint4* rp = reinterpret_cast<uint4*>(smem_raw + warp * 6144);
    unsigned* mw = reinterpret_cast<unsigned*>(smem_raw + RING_BYTES) + warp * 32;
    unsigned short* cw =
        reinterpret_cast<unsigned short*>(smem_raw + RING_BYTES + MSK_BYTES) + warp * 88;
    const unsigned ring_s = (unsigned)__cvta_generic_to_shared(rp);

    // Prologue: sign masks -> smem, then flat 12-bit code sequence
    {
        const float* srow = s + (size_t)b * NSITES;
        #pragma unroll 8
        for (int j = 0; j < 32; j++)
            mw[j] = __ballot_sync(0xffffffffu, srow[j * 32 + lane] > 0.f);
    }
    __syncwarp();
    for (int t = lane; t < 85; t += 32) {
        const int bit = 12 * t, w = bit >> 5, sh = bit & 31;
        const unsigned lo = mw[w];
        const unsigned hi = (w < 31) ? mw[w + 1] : 0u;
        cw[t] = (unsigned short)(__funnelshift_r(lo, hi, sh) & 0xFFFu);
    }
    if (lane == 0) {
        cw[85] = (unsigned short)(N12 + (mw[31] >> 28));   // 4-site tail
        cw[86] = 0; cw[87] = 0;
    }
    __syncwarp();

    // Init M = I in C-fragment layout
    float x[32];
    #pragma unroll
    for (int mt = 0; mt < 2; mt++)
        #pragma unroll
        for (int nt = 0; nt < 4; nt++)
            #pragma unroll
            for (int i = 0; i < 4; i++) {
                const int row = g + 8 * (i >> 1) + 16 * mt;
                const int col = 8 * nt + 2 * tig + (i & 1);
                x[mt*16 + nt*4 + i] = (row == col) ? 1.f : 0.f;
            }

    // Pipeline prologue: stages 0,1 for steps 0,1; A-fragments for step 0
    prefetch_entry(ring_s,        g12_table + (int)cw[0] * 512, lane);
    CP_COMMIT();
    prefetch_entry(ring_s + 2048, g12_table + (int)cw[1] * 512, lane);
    CP_COMMIT();
    unsigned a[16];
    cvt_a(a, x);

    int st = 0;
    for (int k = 0; k < NSTEPS; k++) {
        CP_WAIT1();                            // step k's stage is ready
        const uint4* p = rp + st * 128;
        const uint4 t0 = p[lane],      t1 = p[32 + lane];
        const uint4 t2 = p[64 + lane], t3 = p[96 + lane];
        if (k + 2 < NSTEPS) {                  // prefetch 2 ahead
            int sn = st + 2; if (sn >= 3) sn -= 3;
            prefetch_entry(ring_s + sn * 2048,
                           g12_table + (int)cw[k + 2] * 512, lane);
        }
        CP_COMMIT();                           // always (empty ok)
        mma_half(x, a, 0, t0, t1);             // kc0
        mma_half(x, a, 4, t2, t3);             // kc1
        cvt_a(a, x);                           // next step's A
        st++; if (st == 3) st = 0;
    }

    // trace(M)
    float tr = 0.f;
    #pragma unroll
    for (int mt = 0; mt < 2; mt++)
        #pragma unroll
        for (int nt = 0; nt < 4; nt++)
            #pragma unroll
            for (int i = 0; i < 4; i++) {
                const int row = g + 8 * (i >> 1) + 16 * mt;
                const int col = 8 * nt + 2 * tig + (i & 1);
                if (row == col) tr += x[mt*16 + nt*4 + i];
            }
    #pragma unroll
    for (int off = 16; off; off >>= 1)
        tr += __shfl_xor_sync(0xffffffffu, tr, off);

    if (lane == 0) out[b] = logf(tr);
}

// ---------------------------------------------------------------------------
extern "C" void kernel_launch(void* const* d_in, const int* in_sizes, int n_in,
                              void* d_out, int out_size) {
    const float* s = (const float*)d_in[0];   // [4096, 1024] fp32
    const float* A = (const float*)d_in[1];   // [2, 32, 32] fp32
    float* out = (float*)d_out;               // [4096] fp32

    static bool attr_set = false;
    if (!attr_set) {
        cudaFuncSetAttribute(mps_kernel,
                             cudaFuncAttributeMaxDynamicSharedMemorySize,
                             SMEM_BYTES);
        attr_set = true;
    }

    build_table_kernel<<<NC6 + NC4, 1024>>>(A);
    build12_kernel<<<dim3(64, 8), 1024>>>();
    mps_kernel<<<GRID, NTHREADS, SMEM_BYTES>>>(s, out);
}